// round 1
// baseline (speedup 1.0000x reference)
#include <cuda_runtime.h>
#include <math.h>

// Problem constants
#define B  4
#define S  1024
#define H  1024
#define NH 16
#define DH 64
#define MROWS (B*S)            // 4096
#define H3 (3*H)               // 3072

// ---------------- scratch (static device globals; no allocation) -------------
__device__ float g_qkv[(size_t)MROWS * H3];          // 12.6M f  (qkv for both attentions)
__device__ float g_scores[(size_t)B * NH * S * S];   // 67.1M f  (256 MB, reused)
__device__ float g_a[(size_t)MROWS * H];             // mctx / main ctx
__device__ float g_b[(size_t)MROWS * H];             // ttm_out / tn hidden
__device__ float g_tbase[(size_t)MROWS * H];
__device__ float g_G[(size_t)MROWS * H];             // x @ W1a^T (reused both tn iters)
__device__ float g_t0[MROWS * NH];
__device__ float g_temps[MROWS * 3];
__device__ float g_tw[MROWS];
__device__ float g_twn[MROWS];
__device__ float g_w1bsum[H];
__device__ float g_stats[2];

// ---------------- helpers ---------------------------------------------------
__device__ __forceinline__ float sigmoid_acc(float x) { return 1.0f / (1.0f + expf(-x)); }
__device__ __forceinline__ float gelu_exact(float x) {
    return 0.5f * x * (1.0f + erff(x * 0.70710678118654752f));
}

__device__ __forceinline__ float blockReduceSum256(float v, float* sh) {
    int tid = threadIdx.x;
    sh[tid] = v; __syncthreads();
    #pragma unroll
    for (int s = 128; s > 0; s >>= 1) { if (tid < s) sh[tid] += sh[tid + s]; __syncthreads(); }
    float r = sh[0]; __syncthreads();
    return r;
}

// ---------------- generic tiled SGEMM: C = A @ op(B) (+Cin) -----------------
// TB=true : C[m,n] = sum_k A[m,k] * B[n,k]   (B is [N,K] row-major, "NT")
// TB=false: C[m,n] = sum_k A[m,k] * B[k,n]   (B is [K,N] row-major, "NN")
// Batched via blockIdx.z with split offsets: off = (z/zdiv)*s1 + (z%zdiv)*s2.
// All of M, N multiples of 64 and K multiple of 16 in this problem.
#define BM 64
#define BN 64
#define BKK 16

template<bool TB>
__global__ void sgemm_k(const float* __restrict__ A, const float* __restrict__ Bm,
                        const float* __restrict__ Cin, float* __restrict__ C,
                        int M, int N, int K, int lda, int ldb, int ldc,
                        int zdiv, long sA1, long sA2, long sB1, long sB2,
                        long sC1, long sC2)
{
    int z = blockIdx.z;
    A  += (long)(z / zdiv) * sA1 + (long)(z % zdiv) * sA2;
    Bm += (long)(z / zdiv) * sB1 + (long)(z % zdiv) * sB2;
    long cOff = (long)(z / zdiv) * sC1 + (long)(z % zdiv) * sC2;
    C += cOff;
    if (Cin) Cin += cOff;

    __shared__ float As[BKK][BM + 4];
    __shared__ float Bs[BKK][BN + 4];

    int tid = threadIdx.x;            // 256 threads
    int tx = tid & 15, ty = tid >> 4; // 16x16
    int m0 = blockIdx.y * BM, n0 = blockIdx.x * BN;

    float acc[4][4] = {};
    for (int k0 = 0; k0 < K; k0 += BKK) {
        #pragma unroll
        for (int i = 0; i < 4; i++) {
            int idx = tid + i * 256;
            int r = idx >> 4, c = idx & 15;
            As[c][r] = A[(long)(m0 + r) * lda + (k0 + c)];
        }
        if (TB) {
            #pragma unroll
            for (int i = 0; i < 4; i++) {
                int idx = tid + i * 256;
                int r = idx >> 4, c = idx & 15;
                Bs[c][r] = Bm[(long)(n0 + r) * ldb + (k0 + c)];
            }
        } else {
            #pragma unroll
            for (int i = 0; i < 4; i++) {
                int idx = tid + i * 256;
                int kk = idx >> 6, n = idx & 63;
                Bs[kk][n] = Bm[(long)(k0 + kk) * ldb + (n0 + n)];
            }
        }
        __syncthreads();
        #pragma unroll
        for (int kk = 0; kk < BKK; kk++) {
            float4 ra = *(const float4*)&As[kk][ty * 4];
            float4 rb = *(const float4*)&Bs[kk][tx * 4];
            float av[4] = {ra.x, ra.y, ra.z, ra.w};
            float bv[4] = {rb.x, rb.y, rb.z, rb.w};
            #pragma unroll
            for (int i = 0; i < 4; i++)
                #pragma unroll
                for (int j = 0; j < 4; j++)
                    acc[i][j] += av[i] * bv[j];
        }
        __syncthreads();
    }
    #pragma unroll
    for (int i = 0; i < 4; i++) {
        int m = m0 + ty * 4 + i;
        #pragma unroll
        for (int j = 0; j < 4; j++) {
            int n = n0 + tx * 4 + j;
            float v = acc[i][j];
            if (Cin) v += Cin[(long)m * ldc + n];
            C[(long)m * ldc + n] = v;
        }
    }
}

// ---------------- softmax over rows of scores (1024 cols) -------------------
// pre-scale = scale * (twn ? twn[b*S + q] : 1)
__global__ void softmax_k(float* __restrict__ Sc, const float* __restrict__ twn, float scale)
{
    long row = blockIdx.x;                 // (b*NH + h)*S + q, 65536 rows
    float pre = scale;
    if (twn) {
        int q = (int)(row & (S - 1));
        int b = (int)(row >> 14);          // row / (NH*S)
        pre *= twn[b * S + q];
    }
    float* p = Sc + row * S;
    int tid = threadIdx.x;                 // 256
    float4 v = ((float4*)p)[tid];
    v.x *= pre; v.y *= pre; v.z *= pre; v.w *= pre;
    __shared__ float sh[256];
    float mx = fmaxf(fmaxf(v.x, v.y), fmaxf(v.z, v.w));
    sh[tid] = mx; __syncthreads();
    #pragma unroll
    for (int s = 128; s > 0; s >>= 1) { if (tid < s) sh[tid] = fmaxf(sh[tid], sh[tid + s]); __syncthreads(); }
    mx = sh[0]; __syncthreads();
    v.x = __expf(v.x - mx); v.y = __expf(v.y - mx);
    v.z = __expf(v.z - mx); v.w = __expf(v.w - mx);
    float sm = v.x + v.y + v.z + v.w;
    sh[tid] = sm; __syncthreads();
    #pragma unroll
    for (int s = 128; s > 0; s >>= 1) { if (tid < s) sh[tid] += sh[tid + s]; __syncthreads(); }
    float inv = 1.0f / sh[0];
    v.x *= inv; v.y *= inv; v.z *= inv; v.w *= inv;
    ((float4*)p)[tid] = v;
}

// ------- ttm: y = ttm_out_row @ wt^T ; t0 = 1 + 0.1*(sigmoid(LN16(y)) - .5) --
__global__ void ttm_k(const float* __restrict__ ttm_out, const float* __restrict__ wt,
                      const float* __restrict__ g, const float* __restrict__ b,
                      float* __restrict__ t0)
{
    int row = blockIdx.x;                 // 4096
    int tid = threadIdx.x;                // 512 = 16 warps
    int w = tid >> 5, lane = tid & 31;
    const float* xr = ttm_out + (long)row * H;
    const float* wr = wt + (long)w * H;
    float s = 0.0f;
    for (int k = lane; k < H; k += 32) s += xr[k] * wr[k];
    #pragma unroll
    for (int o = 16; o; o >>= 1) s += __shfl_xor_sync(0xffffffffu, s, o);
    __shared__ float ys[NH];
    if (lane == 0) ys[w] = s;
    __syncthreads();
    if (tid < NH) {
        float m = 0.0f;
        #pragma unroll
        for (int i = 0; i < NH; i++) m += ys[i];
        m *= (1.0f / NH);
        float v = 0.0f;
        #pragma unroll
        for (int i = 0; i < NH; i++) { float d = ys[i] - m; v += d * d; }
        v *= (1.0f / NH);
        float xn = (ys[tid] - m) * rsqrtf(v + 1e-5f) * g[tid] + b[tid];
        float sg = sigmoid_acc(xn);
        t0[row * NH + tid] = 1.0f + 0.1f * (sg - 0.5f);
    }
}

// ------- thp: T_base = sigmoid(gelu(LN(t0 @ thp_w^T + thp_b))) --------------
__global__ void thp_k(const float* __restrict__ t0, const float* __restrict__ W,
                      const float* __restrict__ bias, const float* __restrict__ g,
                      const float* __restrict__ b, float* __restrict__ tb,
                      float* __restrict__ temps)
{
    int row = blockIdx.x, tid = threadIdx.x; // 256
    __shared__ float t0s[NH];
    __shared__ float red[256];
    if (tid < NH) t0s[tid] = t0[row * NH + tid];
    __syncthreads();
    float pre[4], lsum = 0.0f, lsq = 0.0f;
    #pragma unroll
    for (int j = 0; j < 4; j++) {
        int h = tid + j * 256;
        const float* wr = W + (long)h * NH;
        float s = bias[h];
        #pragma unroll
        for (int n = 0; n < NH; n++) s += t0s[n] * wr[n];
        pre[j] = s; lsum += s; lsq += s * s;
    }
    float tot = blockReduceSum256(lsum, red);
    float tot2 = blockReduceSum256(lsq, red);
    float m = tot * (1.0f / H);
    float var = tot2 * (1.0f / H) - m * m;
    float rs = rsqrtf(var + 1e-5f);
    #pragma unroll
    for (int j = 0; j < 4; j++) {
        int h = tid + j * 256;
        float xn = (pre[j] - m) * rs * g[h] + b[h];
        float out = sigmoid_acc(gelu_exact(xn));
        tb[(long)row * H + h] = out;
        if (h == 0) temps[row * 3 + 0] = out;
    }
}

// ------- temp_net LN+gelu; two modes ----------------------------------------
// Ti == nullptr: pre = P[row,h] + bias[h]
// Ti != nullptr: pre = G[row,h] + Ti[row*3]*wsum[h] + bias[h]   (broadcast T_base)
__global__ void tnln_k(const float* __restrict__ P, const float* __restrict__ G,
                       const float* __restrict__ Ti, const float* __restrict__ wsum,
                       const float* __restrict__ bias, const float* __restrict__ g,
                       const float* __restrict__ b, float* __restrict__ out)
{
    int row = blockIdx.x, tid = threadIdx.x; // 256
    __shared__ float red[256];
    float ti = Ti ? Ti[row * 3] : 0.0f;
    float pre[4], lsum = 0.0f, lsq = 0.0f;
    #pragma unroll
    for (int j = 0; j < 4; j++) {
        int h = tid + j * 256;
        float s = bias[h];
        if (Ti) s += G[(long)row * H + h] + ti * wsum[h];
        else    s += P[(long)row * H + h];
        pre[j] = s; lsum += s; lsq += s * s;
    }
    float tot = blockReduceSum256(lsum, red);
    float tot2 = blockReduceSum256(lsq, red);
    float m = tot * (1.0f / H);
    float var = tot2 * (1.0f / H) - m * m;
    float rs = rsqrtf(var + 1e-5f);
    #pragma unroll
    for (int j = 0; j < 4; j++) {
        int h = tid + j * 256;
        float xn = (pre[j] - m) * rs * g[h] + b[h];
        out[(long)row * H + h] = gelu_exact(xn);
    }
}

// ------- Ti = sigmoid(sigmoid(h_row . w2 + b2)) -----------------------------
__global__ void rowdot_k(const float* __restrict__ Hh, const float* __restrict__ w2,
                         const float* __restrict__ b2, float* __restrict__ temps, int slot)
{
    int row = blockIdx.x, tid = threadIdx.x; // 256
    __shared__ float red[256];
    const float4* hr = (const float4*)(Hh + (long)row * H);
    const float4* wr = (const float4*)w2;
    float4 a = hr[tid], w = wr[tid];
    float s = a.x * w.x + a.y * w.y + a.z * w.z + a.w * w.w;
    float tot = blockReduceSum256(s, red);
    if (tid == 0) {
        float y = tot + b2[0];
        temps[row * 3 + slot] = sigmoid_acc(sigmoid_acc(y));
    }
}

// ------- rowsum of W1b = tn_w1[:, H:2H] -------------------------------------
__global__ void w1bsum_k(const float* __restrict__ W1, float* __restrict__ ws)
{
    int h = blockIdx.x, tid = threadIdx.x; // 256
    __shared__ float red[256];
    const float* r = W1 + (long)h * (2 * H) + H;
    float s = r[tid] + r[tid + 256] + r[tid + 512] + r[tid + 768];
    float tot = blockReduceSum256(s, red);
    if (tid == 0) ws[h] = tot;
}

// ------- tw + global mean/std (two-pass, single block) ----------------------
__global__ void stats_k(const float* __restrict__ temps, float* __restrict__ tw,
                        float* __restrict__ st)
{
    __shared__ float sh[1024];
    __shared__ float twsh[MROWS];
    int tid = threadIdx.x; // 1024
    float ls = 0.0f;
    for (int i = tid; i < MROWS; i += 1024) {
        float t = (temps[i * 3] + temps[i * 3 + 1] + temps[i * 3 + 2]) * (1.0f / 3.0f);
        twsh[i] = t; tw[i] = t; ls += t;
    }
    sh[tid] = ls; __syncthreads();
    for (int s = 512; s > 0; s >>= 1) { if (tid < s) sh[tid] += sh[tid + s]; __syncthreads(); }
    float mu = sh[0] * (1.0f / MROWS); __syncthreads();
    float lv = 0.0f;
    for (int i = tid; i < MROWS; i += 1024) { float d = twsh[i] - mu; lv += d * d; }
    sh[tid] = lv; __syncthreads();
    for (int s = 512; s > 0; s >>= 1) { if (tid < s) sh[tid] += sh[tid + s]; __syncthreads(); }
    if (tid == 0) {
        float var = sh[0] * (1.0f / MROWS);
        const double Nt = (double)B * NH * (double)S * (double)S; // 67108864
        float stdu = sqrtf(var * (float)(Nt / (Nt - 1.0)));
        st[0] = mu; st[1] = stdu;
    }
}

// ------- twn + write scale_temps output region ------------------------------
__global__ void twn_k(const float* __restrict__ tw, const float* __restrict__ st,
                      const float* __restrict__ temps, float* __restrict__ twn,
                      float* __restrict__ out2)
{
    int i = blockIdx.x * 256 + threadIdx.x; // 4096
    float mu = st[0], sd = st[1];
    twn[i] = 1.0f + (tw[i] - mu) / (sd + 1.1920929e-7f);
    int b = i >> 10, s = i & 1023;
    out2[(long)b * 3 * S + 0 * S + s] = temps[i * 3 + 0];
    out2[(long)b * 3 * S + 1 * S + s] = temps[i * 3 + 1];
    out2[(long)b * 3 * S + 2 * S + s] = temps[i * 3 + 2];
}

// ---------------------------------------------------------------------------
extern "C" void kernel_launch(void* const* d_in, const int* in_sizes, int n_in,
                              void* d_out, int out_size)
{
    const float* x        = (const float*)d_in[0];
    const float* wq       = (const float*)d_in[1];
    const float* wk       = (const float*)d_in[2];
    const float* wv       = (const float*)d_in[3];
    const float* wo       = (const float*)d_in[4];
    const float* mha_in_w = (const float*)d_in[5];
    const float* mha_out_w= (const float*)d_in[6];
    const float* wt       = (const float*)d_in[7];
    const float* ttm_g    = (const float*)d_in[8];
    const float* ttm_b    = (const float*)d_in[9];
    const float* thp_w    = (const float*)d_in[10];
    const float* thp_b    = (const float*)d_in[11];
    const float* thp_g    = (const float*)d_in[12];
    const float* thp_bb   = (const float*)d_in[13];
    const float* tn_w1    = (const float*)d_in[14];
    const float* tn_b1    = (const float*)d_in[15];
    const float* tn_g     = (const float*)d_in[16];
    const float* tn_bb    = (const float*)d_in[17];
    const float* tn_w2    = (const float*)d_in[18];
    const float* tn_b2    = (const float*)d_in[19];
    float* out = (float*)d_out;

    float *qkv, *scores, *a, *bbuf, *tb, *G, *t0, *temps, *tw, *twn, *wsum, *stats;
    cudaGetSymbolAddress((void**)&qkv,   g_qkv);
    cudaGetSymbolAddress((void**)&scores,g_scores);
    cudaGetSymbolAddress((void**)&a,     g_a);
    cudaGetSymbolAddress((void**)&bbuf,  g_b);
    cudaGetSymbolAddress((void**)&tb,    g_tbase);
    cudaGetSymbolAddress((void**)&G,     g_G);
    cudaGetSymbolAddress((void**)&t0,    g_t0);
    cudaGetSymbolAddress((void**)&temps, g_temps);
    cudaGetSymbolAddress((void**)&tw,    g_tw);
    cudaGetSymbolAddress((void**)&twn,   g_twn);
    cudaGetSymbolAddress((void**)&wsum,  g_w1bsum);
    cudaGetSymbolAddress((void**)&stats, g_stats);

    const long SH3 = (long)S * H3;            // per-batch stride in qkv
    const long SS  = (long)S * S;             // per-head scores stride
    const long SH  = (long)S * H;

    // ---- temperature module MHA ----
    // qkv = x @ mha_in_w^T   [4096, 3072]
    sgemm_k<true><<<dim3(H3 / 64, MROWS / 64, 1), 256>>>(
        x, mha_in_w, nullptr, qkv, MROWS, H3, H, H, H, H3, 1, 0, 0, 0, 0, 0, 0);
    // scores = q @ k^T per (b,h)
    sgemm_k<true><<<dim3(S / 64, S / 64, B * NH), 256>>>(
        qkv, qkv + H, nullptr, scores, S, S, DH, H3, H3, S,
        NH, SH3, DH, SH3, DH, (long)NH * SS, SS);
    softmax_k<<<B * NH * S, 256>>>(scores, nullptr, 0.125f);
    // mctx = probs @ v  -> g_a (head-interleaved [B,S,H])
    sgemm_k<false><<<dim3(1, S / 64, B * NH), 256>>>(
        scores, qkv + 2 * H, nullptr, a, S, DH, S, S, H3, H,
        NH, (long)NH * SS, SS, SH3, DH, SH, DH);
    // ttm_out = mctx @ mha_out_w^T -> g_b
    sgemm_k<true><<<dim3(H / 64, MROWS / 64, 1), 256>>>(
        a, mha_out_w, nullptr, bbuf, MROWS, H, H, H, H, H, 1, 0, 0, 0, 0, 0, 0);
    // t0
    ttm_k<<<MROWS, 512>>>(bbuf, wt, ttm_g, ttm_b, t0);
    // T_base (thp)
    thp_k<<<MROWS, 256>>>(t0, thp_w, thp_b, thp_g, thp_bb, tb, temps);

    // ---- temp_net ----
    w1bsum_k<<<H, 256>>>(tn_w1, wsum);
    // G = x @ W1a^T
    sgemm_k<true><<<dim3(H / 64, MROWS / 64, 1), 256>>>(
        x, tn_w1, nullptr, G, MROWS, H, H, H, 2 * H, H, 1, 0, 0, 0, 0, 0, 0);
    // iter 1: pre = G + T_base @ W1b^T
    sgemm_k<true><<<dim3(H / 64, MROWS / 64, 1), 256>>>(
        tb, tn_w1 + H, G, bbuf, MROWS, H, H, H, 2 * H, H, 1, 0, 0, 0, 0, 0, 0);
    tnln_k<<<MROWS, 256>>>(bbuf, nullptr, nullptr, nullptr, tn_b1, tn_g, tn_bb, bbuf);
    rowdot_k<<<MROWS, 256>>>(bbuf, tn_w2, tn_b2, temps, 1);
    // iter 2: T_base broadcast -> pre = G + Ti*wsum
    tnln_k<<<MROWS, 256>>>(nullptr, G, temps + 1, wsum, tn_b1, tn_g, tn_bb, bbuf);
    rowdot_k<<<MROWS, 256>>>(bbuf, tn_w2, tn_b2, temps, 2);

    // ---- temperature weights ----
    stats_k<<<1, 1024>>>(temps, tw, stats);
    twn_k<<<MROWS / 256, 256>>>(tw, stats, temps, twn, out + (long)MROWS * H);

    // ---- main attention ----
    sgemm_k<true><<<dim3(H / 64, MROWS / 64, 1), 256>>>(
        x, wq, nullptr, qkv, MROWS, H, H, H, H, H3, 1, 0, 0, 0, 0, 0, 0);
    sgemm_k<true><<<dim3(H / 64, MROWS / 64, 1), 256>>>(
        x, wk, nullptr, qkv + H, MROWS, H, H, H, H, H3, 1, 0, 0, 0, 0, 0, 0);
    sgemm_k<true><<<dim3(H / 64, MROWS / 64, 1), 256>>>(
        x, wv, nullptr, qkv + 2 * H, MROWS, H, H, H, H, H3, 1, 0, 0, 0, 0, 0, 0);
    sgemm_k<true><<<dim3(S / 64, S / 64, B * NH), 256>>>(
        qkv, qkv + H, nullptr, scores, S, S, DH, H3, H3, S,
        NH, SH3, DH, SH3, DH, (long)NH * SS, SS);
    softmax_k<<<B * NH * S, 256>>>(scores, twn, 0.125f);
    sgemm_k<false><<<dim3(1, S / 64, B * NH), 256>>>(
        scores, qkv + 2 * H, nullptr, a, S, DH, S, S, H3, H,
        NH, (long)NH * SS, SS, SH3, DH, SH, DH);
    // context = ctx @ wo^T  -> out[0 : 4096*1024]
    sgemm_k<true><<<dim3(H / 64, MROWS / 64, 1), 256>>>(
        a, wo, nullptr, out, MROWS, H, H, H, H, H, 1, 0, 0, 0, 0, 0, 0);
}